// round 1
// baseline (speedup 1.0000x reference)
#include <cuda_runtime.h>
#include <math.h>

#define BB   8
#define SSEQ 4096
#define HD   768
#define CBLK 64
#define NBLK 64

// ---- device scratch (allocation-free rule: __device__ globals) ----
__device__ float g_Q[(size_t)BB*SSEQ*HD];
__device__ float g_K[(size_t)BB*SSEQ*HD];
__device__ float g_V[(size_t)BB*SSEQ*HD];
__device__ float g_a[BB*HD];
__device__ float g_State[2][(size_t)BB*HD*HD];

// ---------------------------------------------------------------
// zero the initial state buffer + the gate accumulator every call
// ---------------------------------------------------------------
__global__ void zero_kernel() {
    size_t idx = (size_t)blockIdx.x * blockDim.x + threadIdx.x;
    size_t N = (size_t)BB * HD * HD;
    for (size_t i = idx; i < N; i += (size_t)gridDim.x * blockDim.x)
        g_State[0][i] = 0.0f;
    if (idx < BB * HD) g_a[idx] = 0.0f;
}

// ---------------------------------------------------------------
// QKV: Y = x @ W for W in {Wq, Wk, Wv}. 128x128 tile, K-chunk 8,
// 256 threads, 8x8 register microtile.
// ---------------------------------------------------------------
__global__ __launch_bounds__(256) void qkv_kernel(
    const float* __restrict__ x,
    const float* __restrict__ Wq,
    const float* __restrict__ Wk,
    const float* __restrict__ Wv)
{
    __shared__ float As[8][132];
    __shared__ float Bs[8][132];
    const float* W  = (blockIdx.z == 0) ? Wq : ((blockIdx.z == 1) ? Wk : Wv);
    float* out      = (blockIdx.z == 0) ? g_Q : ((blockIdx.z == 1) ? g_K : g_V);
    int m0 = blockIdx.x * 128;
    int n0 = blockIdx.y * 128;
    int t  = threadIdx.x;
    int ra = t >> 1, ca = (t & 1) * 4;     // A tile load coords
    int rb = t >> 5, cb = (t & 31) * 4;    // B tile load coords
    int tx = t & 15, ty = t >> 4;

    const float* Ap = x + (size_t)(m0 + ra) * HD + ca;
    const float* Bp = W + (size_t)rb * HD + n0 + cb;

    float acc[8][8];
#pragma unroll
    for (int i = 0; i < 8; i++)
#pragma unroll
        for (int j = 0; j < 8; j++) acc[i][j] = 0.0f;

    for (int k0 = 0; k0 < HD; k0 += 8) {
        float4 av = *(const float4*)(Ap + k0);
        float4 bv = *(const float4*)(Bp + (size_t)k0 * HD);
        As[ca + 0][ra] = av.x; As[ca + 1][ra] = av.y;
        As[ca + 2][ra] = av.z; As[ca + 3][ra] = av.w;
        *(float4*)&Bs[rb][cb] = bv;
        __syncthreads();
#pragma unroll
        for (int kk = 0; kk < 8; kk++) {
            float a[8], b[8];
            *(float4*)&a[0] = *(const float4*)&As[kk][ty * 8];
            *(float4*)&a[4] = *(const float4*)&As[kk][ty * 8 + 4];
            *(float4*)&b[0] = *(const float4*)&Bs[kk][tx * 8];
            *(float4*)&b[4] = *(const float4*)&Bs[kk][tx * 8 + 4];
#pragma unroll
            for (int i = 0; i < 8; i++)
#pragma unroll
                for (int j = 0; j < 8; j++)
                    acc[i][j] = fmaf(a[i], b[j], acc[i][j]);
        }
        __syncthreads();
    }
#pragma unroll
    for (int i = 0; i < 8; i++) {
        float* op = out + (size_t)(m0 + ty * 8 + i) * HD + n0 + tx * 8;
        *(float4*)op       = make_float4(acc[i][0], acc[i][1], acc[i][2], acc[i][3]);
        *(float4*)(op + 4) = make_float4(acc[i][4], acc[i][5], acc[i][6], acc[i][7]);
    }
}

// ---------------------------------------------------------------
// Gate: a[b,d] = mean_s sigmoid((x@W1)@W2 + b)[b,s,d] ^ (1/16)
// One block = 64 rows of one batch; one warp = 8 rows.
// W1 (768x16) and W2 (16x768) live in dynamic shared memory.
// ---------------------------------------------------------------
__global__ __launch_bounds__(256) void alpha_kernel(
    const float* __restrict__ x,
    const float* __restrict__ W1,
    const float* __restrict__ W2,
    const float* __restrict__ bvec)
{
    extern __shared__ float sm[];
    float* W1s = sm;              // 768*16
    float* W2s = sm + HD * 16;    // 16*768
    int t = threadIdx.x;
    for (int i = t; i < HD * 16; i += 256) { W1s[i] = W1[i]; W2s[i] = W2[i]; }
    __syncthreads();

    int b      = blockIdx.x >> 6;        // 64 blocks per batch
    int rowblk = blockIdx.x & 63;
    int w = t >> 5, lane = t & 31;

    float acc[24];
#pragma unroll
    for (int q = 0; q < 24; q++) acc[q] = 0.0f;

    for (int r = 0; r < 8; r++) {
        int row = rowblk * 64 + w * 8 + r;
        const float* xr = x + ((size_t)b * SSEQ + row) * HD;
        float tp[16];
#pragma unroll
        for (int j = 0; j < 16; j++) tp[j] = 0.0f;
        for (int i = lane; i < HD; i += 32) {
            float xv = xr[i];
            const float* w1r = &W1s[i * 16];
#pragma unroll
            for (int j = 0; j < 16; j++) tp[j] = fmaf(xv, w1r[j], tp[j]);
        }
#pragma unroll
        for (int off = 16; off > 0; off >>= 1)
#pragma unroll
            for (int j = 0; j < 16; j++)
                tp[j] += __shfl_xor_sync(0xffffffffu, tp[j], off);
        // every lane now has the full t[16]
#pragma unroll
        for (int q = 0; q < 24; q++) {
            int d = lane + q * 32;
            float h = bvec[d];
#pragma unroll
            for (int j = 0; j < 16; j++) h = fmaf(tp[j], W2s[j * HD + d], h);
            float sig = 1.0f / (1.0f + expf(-h));
            // sig^(1/16) via 4 square roots (accurate, cheap)
            float v = sqrtf(sqrtf(sqrtf(sqrtf(sig))));
            acc[q] += v;
        }
    }
    const float inv = 1.0f / (float)SSEQ;
#pragma unroll
    for (int q = 0; q < 24; q++) {
        int d = lane + q * 32;
        atomicAdd(&g_a[b * HD + d], acc[q] * inv);
    }
}

// ---------------------------------------------------------------
// Intra-block attention (state-independent, fully parallel):
//   P = q kT ; scores = P * tril * scale ; W = softmax(scores)
//   out[b, nb*64+c, :] = (P + W) @ v     (written, not added)
// Block = (nb, b), 256 threads.
// ---------------------------------------------------------------
__global__ __launch_bounds__(256) void attn_kernel(float* __restrict__ out) {
    __shared__ float Ps[64][65];
    __shared__ float buf[64][68];
    int nb = blockIdx.x, b = blockIdx.y;
    int t = threadIdx.x, tx = t & 15, ty = t >> 4;
    size_t base = ((size_t)b * SSEQ + (size_t)nb * CBLK) * HD;
    const float* Qb = g_Q + base;
    const float* Kb = g_K + base;
    const float* Vb = g_V + base;

    float acc[4][4];
#pragma unroll
    for (int i = 0; i < 4; i++)
#pragma unroll
        for (int j = 0; j < 4; j++) acc[i][j] = 0.0f;

    // P = q @ kT, reduce over h in chunks of 32 (transposed smem tiles)
    for (int h0 = 0; h0 < HD; h0 += 32) {
#pragma unroll
        for (int rr = 0; rr < 2; rr++) {
            int idx = t + rr * 256;
            int c = idx >> 3, hl = (idx & 7) * 4;
            float4 qv = *(const float4*)(Qb + (size_t)c * HD + h0 + hl);
            float4 kv = *(const float4*)(Kb + (size_t)c * HD + h0 + hl);
            buf[hl + 0][c] = qv.x; buf[hl + 1][c] = qv.y;
            buf[hl + 2][c] = qv.z; buf[hl + 3][c] = qv.w;
            buf[32 + hl + 0][c] = kv.x; buf[32 + hl + 1][c] = kv.y;
            buf[32 + hl + 2][c] = kv.z; buf[32 + hl + 3][c] = kv.w;
        }
        __syncthreads();
#pragma unroll
        for (int hh = 0; hh < 32; hh++) {
            float a[4], bf[4];
            *(float4*)a  = *(const float4*)&buf[hh][ty * 4];
            *(float4*)bf = *(const float4*)&buf[32 + hh][tx * 4];
#pragma unroll
            for (int i = 0; i < 4; i++)
#pragma unroll
                for (int j = 0; j < 4; j++)
                    acc[i][j] = fmaf(a[i], bf[j], acc[i][j]);
        }
        __syncthreads();
    }
#pragma unroll
    for (int i = 0; i < 4; i++)
#pragma unroll
        for (int j = 0; j < 4; j++)
            Ps[ty * 4 + i][tx * 4 + j] = acc[i][j];
    __syncthreads();

    // softmax (multiplicative mask: masked entries are 0, NOT -inf), then M2 = P + W
    {
        int w = t >> 5, lane = t & 31;
        const float scale = 1.0f / 27.712813f;  // 1/sqrt(768)
#pragma unroll
        for (int r8 = 0; r8 < 8; r8++) {
            int r = w * 8 + r8;
            float p0 = Ps[r][lane], p1 = Ps[r][lane + 32];
            float s0 = (lane <= r)        ? p0 * scale : 0.0f;
            float s1 = ((lane + 32) <= r) ? p1 * scale : 0.0f;
            float m = fmaxf(s0, s1);
#pragma unroll
            for (int off = 16; off; off >>= 1)
                m = fmaxf(m, __shfl_xor_sync(0xffffffffu, m, off));
            float e0 = expf(s0 - m), e1 = expf(s1 - m);
            float ssum = e0 + e1;
#pragma unroll
            for (int off = 16; off; off >>= 1)
                ssum += __shfl_xor_sync(0xffffffffu, ssum, off);
            float invz = 1.0f / ssum;
            Ps[r][lane]      = p0 + e0 * invz;
            Ps[r][lane + 32] = p1 + e1 * invz;
        }
    }
    __syncthreads();

    // out = M2 @ v, d in tiles of 64
    for (int d0 = 0; d0 < HD; d0 += 64) {
#pragma unroll
        for (int rr = 0; rr < 4; rr++) {
            int idx = t + rr * 256;
            int c = idx >> 4, dl = (idx & 15) * 4;
            *(float4*)&buf[c][dl] = *(const float4*)(Vb + (size_t)c * HD + d0 + dl);
        }
        __syncthreads();
        float o[4][4];
#pragma unroll
        for (int i = 0; i < 4; i++)
#pragma unroll
            for (int j = 0; j < 4; j++) o[i][j] = 0.0f;
        for (int cp = 0; cp < 64; cp++) {
            float a[4], bf[4];
            a[0] = Ps[ty * 4 + 0][cp]; a[1] = Ps[ty * 4 + 1][cp];
            a[2] = Ps[ty * 4 + 2][cp]; a[3] = Ps[ty * 4 + 3][cp];
            *(float4*)bf = *(const float4*)&buf[cp][tx * 4];
#pragma unroll
            for (int i = 0; i < 4; i++)
#pragma unroll
                for (int j = 0; j < 4; j++)
                    o[i][j] = fmaf(a[i], bf[j], o[i][j]);
        }
#pragma unroll
        for (int i = 0; i < 4; i++) {
            float* op = out + base + (size_t)(ty * 4 + i) * HD + d0 + tx * 4;
            *(float4*)op = make_float4(o[i][0], o[i][1], o[i][2], o[i][3]);
        }
        __syncthreads();
    }
}

// ---------------------------------------------------------------
// One scan step (launched 64x, double-buffered state, both tasks
// only READ St_cur):
//   U (yy<12):  St_next[h,d] = St_cur[h,d]*a[d] + sum_c k[c,h] v[c,d]
//   O (yy>=12): out[nb*64+c, d] += a[d] * sum_{h in chunk} q[c,h] St_cur[h,d]
//               (h split into 4 chunks of 192 for load balance; atomicAdd)
// ---------------------------------------------------------------
__global__ __launch_bounds__(256) void step_kernel(int nb, float* __restrict__ out) {
    __shared__ float smA[64][68];
    __shared__ float smB[64][68];
    const float* Sc = g_State[nb & 1];
    float*       Sn = g_State[(nb + 1) & 1];
    int b  = blockIdx.z;
    int dt = blockIdx.x;           // 0..11
    int yy = blockIdx.y;           // 0..15
    int t = threadIdx.x, tx = t & 15, ty = t >> 4;
    int d0 = dt * 64;
    size_t tokbase = ((size_t)b * SSEQ + (size_t)nb * CBLK) * HD;

    if (yy < 12) {
        // ---- state update tile ----
        int h0 = yy * 64;
        const float* Kb = g_K + tokbase;
        const float* Vb = g_V + tokbase;
#pragma unroll
        for (int rr = 0; rr < 4; rr++) {
            int idx = t + rr * 256;
            int c = idx >> 4, l = (idx & 15) * 4;
            *(float4*)&smA[c][l] = *(const float4*)(Kb + (size_t)c * HD + h0 + l);
            *(float4*)&smB[c][l] = *(const float4*)(Vb + (size_t)c * HD + d0 + l);
        }
        __syncthreads();
        float acc[4][4];
#pragma unroll
        for (int i = 0; i < 4; i++)
#pragma unroll
            for (int j = 0; j < 4; j++) acc[i][j] = 0.0f;
        for (int c = 0; c < 64; c++) {
            float a[4], bf[4];
            *(float4*)a  = *(const float4*)&smA[c][ty * 4];
            *(float4*)bf = *(const float4*)&smB[c][tx * 4];
#pragma unroll
            for (int i = 0; i < 4; i++)
#pragma unroll
                for (int j = 0; j < 4; j++)
                    acc[i][j] = fmaf(a[i], bf[j], acc[i][j]);
        }
        const float* ap = g_a + b * HD + d0;
        float aval[4];
#pragma unroll
        for (int j = 0; j < 4; j++) aval[j] = ap[tx * 4 + j];
        size_t sbase = (size_t)b * HD * HD + (size_t)h0 * HD + d0;
#pragma unroll
        for (int i = 0; i < 4; i++) {
            size_t rowo = sbase + (size_t)(ty * 4 + i) * HD + tx * 4;
            float4 sv = *(const float4*)(Sc + rowo);
            float4 nv;
            nv.x = sv.x * aval[0] + acc[i][0];
            nv.y = sv.y * aval[1] + acc[i][1];
            nv.z = sv.z * aval[2] + acc[i][2];
            nv.w = sv.w * aval[3] + acc[i][3];
            *(float4*)(Sn + rowo) = nv;
        }
    } else {
        // ---- output contribution: a[d] * (q @ St_cur) ----
        if (nb == 0) return;  // state is zero on the first step
        int hc = yy - 12;     // 0..3, chunk of 192 h
        const float* Qb = g_Q + tokbase;
        const float* Sb = Sc + (size_t)b * HD * HD;
        float acc[4][4];
#pragma unroll
        for (int i = 0; i < 4; i++)
#pragma unroll
            for (int j = 0; j < 4; j++) acc[i][j] = 0.0f;
        for (int hb = 0; hb < 3; hb++) {
            int h0 = hc * 192 + hb * 64;
#pragma unroll
            for (int rr = 0; rr < 4; rr++) {
                int idx = t + rr * 256;
                int rrow = idx >> 4, l = (idx & 15) * 4;
                float4 qv = *(const float4*)(Qb + (size_t)rrow * HD + h0 + l);
                smA[l + 0][rrow] = qv.x; smA[l + 1][rrow] = qv.y;
                smA[l + 2][rrow] = qv.z; smA[l + 3][rrow] = qv.w;
                *(float4*)&smB[rrow][l] =
                    *(const float4*)(Sb + (size_t)(h0 + rrow) * HD + d0 + l);
            }
            __syncthreads();
            for (int hh = 0; hh < 64; hh++) {
                float a[4], bf[4];
                *(float4*)a  = *(const float4*)&smA[hh][ty * 4];
                *(float4*)bf = *(const float4*)&smB[hh][tx * 4];
#pragma unroll
                for (int i = 0; i < 4; i++)
#pragma unroll
                    for (int j = 0; j < 4; j++)
                        acc[i][j] = fmaf(a[i], bf[j], acc[i][j]);
            }
            __syncthreads();
        }
        const float* ap = g_a + b * HD + d0;
        float aval[4];
#pragma unroll
        for (int j = 0; j < 4; j++) aval[j] = ap[tx * 4 + j];
        size_t obase = tokbase + d0;
#pragma unroll
        for (int i = 0; i < 4; i++)
#pragma unroll
            for (int j = 0; j < 4; j++)
                atomicAdd(&out[obase + (size_t)(ty * 4 + i) * HD + tx * 4 + j],
                          acc[i][j] * aval[j]);
    }
}

// ---------------------------------------------------------------
extern "C" void kernel_launch(void* const* d_in, const int* in_sizes, int n_in,
                              void* d_out, int out_size)
{
    const float* x  = (const float*)d_in[0];
    const float* Wq = (const float*)d_in[1];
    const float* Wk = (const float*)d_in[2];
    const float* Wv = (const float*)d_in[3];
    const float* W1 = (const float*)d_in[4];
    const float* W2 = (const float*)d_in[5];
    const float* bv = (const float*)d_in[6];
    float* out = (float*)d_out;

    zero_kernel<<<4608, 1024>>>();

    qkv_kernel<<<dim3(SSEQ * BB / 128, HD / 128, 3), 256>>>(x, Wq, Wk, Wv);

    cudaFuncSetAttribute((const void*)alpha_kernel,
                         cudaFuncAttributeMaxDynamicSharedMemorySize, 98304);
    alpha_kernel<<<BB * 64, 256, 98304>>>(x, W1, W2, bv);

    attn_kernel<<<dim3(NBLK, BB), 256>>>(out);

    for (int nb = 0; nb < NBLK; nb++)
        step_kernel<<<dim3(12, 16, BB), 256>>>(nb, out);
}

// round 3
// speedup vs baseline: 2.0723x; 2.0723x over previous
#include <cuda_runtime.h>
#include <cuda_bf16.h>
#include <math.h>
#include <stdint.h>

#define BB   8
#define SSEQ 4096
#define HD   768
#define CBLK 64
#define NBLK 64

// ---- device scratch ----
__device__ float g_Q[(size_t)BB*SSEQ*HD];
__device__ float g_K[(size_t)BB*SSEQ*HD];
__device__ float g_V[(size_t)BB*SSEQ*HD];
__device__ float g_a[BB*HD];
__device__ float g_State[2][(size_t)BB*HD*HD];
__device__ __nv_bfloat16 g_xh[(size_t)BB*SSEQ*HD];
__device__ __nv_bfloat16 g_xl[(size_t)BB*SSEQ*HD];
__device__ __nv_bfloat16 g_Wth[3*HD*HD];   // W^T (n-major) hi
__device__ __nv_bfloat16 g_Wtl[3*HD*HD];   // W^T lo

__device__ __forceinline__ uint32_t smem_u32(const void* p) {
    uint32_t a;
    asm("{ .reg .u64 t; cvta.to.shared.u64 t, %1; cvt.u32.u64 %0, t; }"
        : "=r"(a) : "l"(p));
    return a;
}

// ================= conversion kernels =================
__global__ void convert_x_kernel(const float* __restrict__ x) {
    size_t n4 = (size_t)BB * SSEQ * HD / 4;
    for (size_t i = (size_t)blockIdx.x * blockDim.x + threadIdx.x; i < n4;
         i += (size_t)gridDim.x * blockDim.x) {
        float4 v = ((const float4*)x)[i];
        __nv_bfloat16 h0 = __float2bfloat16(v.x);
        __nv_bfloat16 h1 = __float2bfloat16(v.y);
        __nv_bfloat16 h2 = __float2bfloat16(v.z);
        __nv_bfloat16 h3 = __float2bfloat16(v.w);
        __nv_bfloat16 l0 = __float2bfloat16(v.x - __bfloat162float(h0));
        __nv_bfloat16 l1 = __float2bfloat16(v.y - __bfloat162float(h1));
        __nv_bfloat16 l2 = __float2bfloat16(v.z - __bfloat162float(h2));
        __nv_bfloat16 l3 = __float2bfloat16(v.w - __bfloat162float(h3));
        __nv_bfloat162 ph0; ph0.x = h0; ph0.y = h1;
        __nv_bfloat162 ph1; ph1.x = h2; ph1.y = h3;
        __nv_bfloat162 pl0; pl0.x = l0; pl0.y = l1;
        __nv_bfloat162 pl1; pl1.x = l2; pl1.y = l3;
        ((__nv_bfloat162*)g_xh)[2*i]   = ph0;
        ((__nv_bfloat162*)g_xh)[2*i+1] = ph1;
        ((__nv_bfloat162*)g_xl)[2*i]   = pl0;
        ((__nv_bfloat162*)g_xl)[2*i+1] = pl1;
    }
}

__global__ void convert_w_kernel(const float* __restrict__ Wq,
                                 const float* __restrict__ Wk,
                                 const float* __restrict__ Wv) {
    int w = blockIdx.z;
    const float* W = (w == 0) ? Wq : ((w == 1) ? Wk : Wv);
    __nv_bfloat16* th = g_Wth + (size_t)w * HD * HD;
    __nv_bfloat16* tl = g_Wtl + (size_t)w * HD * HD;
    for (int idx = blockIdx.x * 256 + threadIdx.x; idx < HD * HD; idx += gridDim.x * 256) {
        int k = idx / HD, n = idx % HD;
        float v = W[idx];
        __nv_bfloat16 hi = __float2bfloat16(v);
        __nv_bfloat16 lo = __float2bfloat16(v - __bfloat162float(hi));
        th[(size_t)n * HD + k] = hi;
        tl[(size_t)n * HD + k] = lo;
    }
}

// ================= zero =================
__global__ void zero_kernel() {
    size_t idx = (size_t)blockIdx.x * blockDim.x + threadIdx.x;
    size_t N = (size_t)BB * HD * HD;
    for (size_t i = idx; i < N; i += (size_t)gridDim.x * blockDim.x)
        g_State[0][i] = 0.0f;
    if (idx < BB * HD) g_a[idx] = 0.0f;
}

// ================= QKV via mma.sync bf16x3 =================
// CTA tile 128x128, 8 warps (2m x 4n -> warp 64x32), K-chunk 32,
// cp.async double buffer. A = x hi/lo, B = W^T hi/lo (n-major).
#define QKV_STRIDE 40            // smem row stride in bf16 elems (80B)
#define QKV_ARR_BYTES 10240      // 128 * 40 * 2
#define QKV_STAGE_BYTES 40960    // 4 arrays

__device__ __forceinline__ void ldsm_x4(uint32_t (&r)[4], uint32_t addr) {
    asm volatile("ldmatrix.sync.aligned.m8n8.x4.shared.b16 {%0,%1,%2,%3}, [%4];"
                 : "=r"(r[0]), "=r"(r[1]), "=r"(r[2]), "=r"(r[3]) : "r"(addr));
}
__device__ __forceinline__ void mma_bf16(float (&c)[4], const uint32_t a[4],
                                         const uint32_t b0, const uint32_t b1) {
    asm volatile(
        "mma.sync.aligned.m16n8k16.row.col.f32.bf16.bf16.f32 "
        "{%0,%1,%2,%3}, {%4,%5,%6,%7}, {%8,%9}, {%0,%1,%2,%3};"
        : "+f"(c[0]), "+f"(c[1]), "+f"(c[2]), "+f"(c[3])
        : "r"(a[0]), "r"(a[1]), "r"(a[2]), "r"(a[3]), "r"(b0), "r"(b1));
}

__global__ __launch_bounds__(256) void qkv_mma_kernel() {
    extern __shared__ char sm[];
    uint32_t smb = smem_u32(sm);
    int t = threadIdx.x, lane = t & 31, w = t >> 5;
    int wm = w & 1, wn = w >> 1;
    int nb = blockIdx.x * 128;      // n fastest -> L2 reuse of A across n-tiles
    int mb = blockIdx.y * 128;
    int mat = blockIdx.z;
    const __nv_bfloat16* Bh_g = g_Wth + (size_t)mat * HD * HD;
    const __nv_bfloat16* Bl_g = g_Wtl + (size_t)mat * HD * HD;
    float* outp = (mat == 0) ? g_Q : ((mat == 1) ? g_K : g_V);

    float acc[4][4][4];
#pragma unroll
    for (int i = 0; i < 4; i++)
#pragma unroll
        for (int j = 0; j < 4; j++)
#pragma unroll
            for (int q = 0; q < 4; q++) acc[i][j][q] = 0.0f;

    // ---- async stage loader: 2048 16B chunks, 8 per thread ----
    auto issue = [&](int s, int k0) {
#pragma unroll
        for (int q = 0; q < 8; q++) {
            int id = t + q * 256;
            int arr = id >> 9, rem = id & 511;
            int row = rem >> 2, c = (rem & 3) * 8;
            const __nv_bfloat16* gp;
            if (arr == 0)      gp = g_xh + (size_t)(mb + row) * HD + k0 + c;
            else if (arr == 1) gp = g_xl + (size_t)(mb + row) * HD + k0 + c;
            else if (arr == 2) gp = Bh_g + (size_t)(nb + row) * HD + k0 + c;
            else               gp = Bl_g + (size_t)(nb + row) * HD + k0 + c;
            uint32_t sa = smb + s * QKV_STAGE_BYTES + arr * QKV_ARR_BYTES
                        + (row * QKV_STRIDE + c) * 2;
            asm volatile("cp.async.cg.shared.global [%0], [%1], 16;"
                         :: "r"(sa), "l"(gp));
        }
        asm volatile("cp.async.commit_group;");
    };

    issue(0, 0);

    // ldmatrix lane addressing
    int aRow = wm * 64 + (lane & 15);          // + mf*16
    int aColSel = (lane >> 4) * 8;             // + kk*16
    int bRow = wn * 32 + (lane & 7) + ((lane >> 4) << 3);  // + ng*16
    int bColSel = ((lane >> 3) & 1) * 8;       // + kk*16

    for (int it = 0; it < 24; it++) {
        int s = it & 1;
        if (it + 1 < 24) {
            issue(1 - s, (it + 1) * 32);
            asm volatile("cp.async.wait_group 1;");
        } else {
            asm volatile("cp.async.wait_group 0;");
        }
        __syncthreads();

        uint32_t stage = smb + s * QKV_STAGE_BYTES;
#pragma unroll
        for (int kk = 0; kk < 2; kk++) {
            int aCol = kk * 16 + aColSel;
            int bCol = kk * 16 + bColSel;
            uint32_t ah[4][4], al[4][4];
#pragma unroll
            for (int mf = 0; mf < 4; mf++) {
                uint32_t addr = stage + ((aRow + mf * 16) * QKV_STRIDE + aCol) * 2;
                ldsm_x4(ah[mf], addr);
                ldsm_x4(al[mf], addr + QKV_ARR_BYTES);
            }
            uint32_t bh[4][2], bl[4][2];
#pragma unroll
            for (int ng = 0; ng < 2; ng++) {
                uint32_t addr = stage + 2 * QKV_ARR_BYTES
                              + ((bRow + ng * 16) * QKV_STRIDE + bCol) * 2;
                uint32_t r[4];
                ldsm_x4(r, addr);
                bh[2*ng][0] = r[0]; bh[2*ng][1] = r[1];
                bh[2*ng+1][0] = r[2]; bh[2*ng+1][1] = r[3];
                ldsm_x4(r, addr + QKV_ARR_BYTES);
                bl[2*ng][0] = r[0]; bl[2*ng][1] = r[1];
                bl[2*ng+1][0] = r[2]; bl[2*ng+1][1] = r[3];
            }
#pragma unroll
            for (int mf = 0; mf < 4; mf++)
#pragma unroll
                for (int nf = 0; nf < 4; nf++) {
                    mma_bf16(acc[mf][nf], ah[mf], bh[nf][0], bh[nf][1]);
                    mma_bf16(acc[mf][nf], ah[mf], bl[nf][0], bl[nf][1]);
                    mma_bf16(acc[mf][nf], al[mf], bh[nf][0], bh[nf][1]);
                }
        }
        __syncthreads();
    }

    // ---- epilogue: c0,c1 at (g, 2tig), c2,c3 at (g+8, 2tig) ----
    int g = lane >> 2, tig = lane & 3;
#pragma unroll
    for (int mf = 0; mf < 4; mf++) {
#pragma unroll
        for (int nf = 0; nf < 4; nf++) {
            int row = mb + wm * 64 + mf * 16 + g;
            int col = nb + wn * 32 + nf * 8 + tig * 2;
            float* p0 = outp + (size_t)row * HD + col;
            float* p1 = outp + (size_t)(row + 8) * HD + col;
            *(float2*)p0 = make_float2(acc[mf][nf][0], acc[mf][nf][1]);
            *(float2*)p1 = make_float2(acc[mf][nf][2], acc[mf][nf][3]);
        }
    }
}

// ================= gate alpha =================
__global__ __launch_bounds__(256) void alpha_kernel(
    const float* __restrict__ x,
    const float* __restrict__ W1,
    const float* __restrict__ W2,
    const float* __restrict__ bvec)
{
    extern __shared__ float smf[];
    float* W1s = smf;
    float* W2s = smf + HD * 16;
    int t = threadIdx.x;
    for (int i = t; i < HD * 16; i += 256) { W1s[i] = W1[i]; W2s[i] = W2[i]; }
    __syncthreads();

    int b = blockIdx.x >> 6;
    int rowblk = blockIdx.x & 63;
    int w = t >> 5, lane = t & 31;

    float acc[24];
#pragma unroll
    for (int q = 0; q < 24; q++) acc[q] = 0.0f;

    for (int r = 0; r < 8; r++) {
        int row = rowblk * 64 + w * 8 + r;
        const float* xr = x + ((size_t)b * SSEQ + row) * HD;
        float tp[16];
#pragma unroll
        for (int j = 0; j < 16; j++) tp[j] = 0.0f;
        for (int i = lane; i < HD; i += 32) {
            float xv = xr[i];
            const float* w1r = &W1s[i * 16];
#pragma unroll
            for (int j = 0; j < 16; j++) tp[j] = fmaf(xv, w1r[j], tp[j]);
        }
#pragma unroll
        for (int off = 16; off > 0; off >>= 1)
#pragma unroll
            for (int j = 0; j < 16; j++)
                tp[j] += __shfl_xor_sync(0xffffffffu, tp[j], off);
#pragma unroll
        for (int q = 0; q < 24; q++) {
            int d = lane + q * 32;
            float h = bvec[d];
#pragma unroll
            for (int j = 0; j < 16; j++) h = fmaf(tp[j], W2s[j * HD + d], h);
            float sig = 1.0f / (1.0f + expf(-h));
            float v = sqrtf(sqrtf(sqrtf(sqrtf(sig))));
            acc[q] += v;
        }
    }
    const float inv = 1.0f / (float)SSEQ;
#pragma unroll
    for (int q = 0; q < 24; q++) {
        int d = lane + q * 32;
        atomicAdd(&g_a[b * HD + d], acc[q] * inv);
    }
}

// ================= intra-block attention =================
__global__ __launch_bounds__(256) void attn_kernel(float* __restrict__ out) {
    __shared__ float Ps[64][65];
    __shared__ float buf[64][68];
    int nb = blockIdx.x, b = blockIdx.y;
    int t = threadIdx.x, tx = t & 15, ty = t >> 4;
    size_t base = ((size_t)b * SSEQ + (size_t)nb * CBLK) * HD;
    const float* Qb = g_Q + base;
    const float* Kb = g_K + base;
    const float* Vb = g_V + base;

    float acc[4][4];
#pragma unroll
    for (int i = 0; i < 4; i++)
#pragma unroll
        for (int j = 0; j < 4; j++) acc[i][j] = 0.0f;

    for (int h0 = 0; h0 < HD; h0 += 32) {
#pragma unroll
        for (int rr = 0; rr < 2; rr++) {
            int idx = t + rr * 256;
            int c = idx >> 3, hl = (idx & 7) * 4;
            float4 qv = *(const float4*)(Qb + (size_t)c * HD + h0 + hl);
            float4 kv = *(const float4*)(Kb + (size_t)c * HD + h0 + hl);
            buf[hl + 0][c] = qv.x; buf[hl + 1][c] = qv.y;
            buf[hl + 2][c] = qv.z; buf[hl + 3][c] = qv.w;
            buf[32 + hl + 0][c] = kv.x; buf[32 + hl + 1][c] = kv.y;
            buf[32 + hl + 2][c] = kv.z; buf[32 + hl + 3][c] = kv.w;
        }
        __syncthreads();
#pragma unroll
        for (int hh = 0; hh < 32; hh++) {
            float a[4], bf[4];
            *(float4*)a  = *(const float4*)&buf[hh][ty * 4];
            *(float4*)bf = *(const float4*)&buf[32 + hh][tx * 4];
#pragma unroll
            for (int i = 0; i < 4; i++)
#pragma unroll
                for (int j = 0; j < 4; j++)
                    acc[i][j] = fmaf(a[i], bf[j], acc[i][j]);
        }
        __syncthreads();
    }
#pragma unroll
    for (int i = 0; i < 4; i++)
#pragma unroll
        for (int j = 0; j < 4; j++)
            Ps[ty * 4 + i][tx * 4 + j] = acc[i][j];
    __syncthreads();

    {
        int w = t >> 5, lane = t & 31;
        const float scale = 1.0f / 27.712813f;
#pragma unroll
        for (int r8 = 0; r8 < 8; r8++) {
            int r = w * 8 + r8;
            float p0 = Ps[r][lane], p1 = Ps[r][lane + 32];
            float s0 = (lane <= r)        ? p0 * scale : 0.0f;
            float s1 = ((lane + 32) <= r) ? p1 * scale : 0.0f;
            float m = fmaxf(s0, s1);
#pragma unroll
            for (int off = 16; off; off >>= 1)
                m = fmaxf(m, __shfl_xor_sync(0xffffffffu, m, off));
            float e0 = expf(s0 - m), e1 = expf(s1 - m);
            float ssum = e0 + e1;
#pragma unroll
            for (int off = 16; off; off >>= 1)
                ssum += __shfl_xor_sync(0xffffffffu, ssum, off);
            float invz = 1.0f / ssum;
            Ps[r][lane]      = p0 + e0 * invz;
            Ps[r][lane + 32] = p1 + e1 * invz;
        }
    }
    __syncthreads();

    for (int d0 = 0; d0 < HD; d0 += 64) {
#pragma unroll
        for (int rr = 0; rr < 4; rr++) {
            int idx = t + rr * 256;
            int c = idx >> 4, dl = (idx & 15) * 4;
            *(float4*)&buf[c][dl] = *(const float4*)(Vb + (size_t)c * HD + d0 + dl);
        }
        __syncthreads();
        float o[4][4];
#pragma unroll
        for (int i = 0; i < 4; i++)
#pragma unroll
            for (int j = 0; j < 4; j++) o[i][j] = 0.0f;
        for (int cp = 0; cp < 64; cp++) {
            float a[4], bf[4];
            a[0] = Ps[ty * 4 + 0][cp]; a[1] = Ps[ty * 4 + 1][cp];
            a[2] = Ps[ty * 4 + 2][cp]; a[3] = Ps[ty * 4 + 3][cp];
            *(float4*)bf = *(const float4*)&buf[cp][tx * 4];
#pragma unroll
            for (int i = 0; i < 4; i++)
#pragma unroll
                for (int j = 0; j < 4; j++)
                    o[i][j] = fmaf(a[i], bf[j], o[i][j]);
        }
#pragma unroll
        for (int i = 0; i < 4; i++) {
            float* op = out + base + (size_t)(ty * 4 + i) * HD + d0 + tx * 4;
            *(float4*)op = make_float4(o[i][0], o[i][1], o[i][2], o[i][3]);
        }
        __syncthreads();
    }
}

// ================= scan step =================
__global__ __launch_bounds__(256) void step_kernel(int nb, float* __restrict__ out) {
    __shared__ float smA[64][68];
    __shared__ float smB[64][68];
    const float* Sc = g_State[nb & 1];
    float*       Sn = g_State[(nb + 1) & 1];
    int b  = blockIdx.z;
    int dt = blockIdx.x;
    int yy = blockIdx.y;
    int t = threadIdx.x, tx = t & 15, ty = t >> 4;
    int d0 = dt * 64;
    size_t tokbase = ((size_t)b * SSEQ + (size_t)nb * CBLK) * HD;

    if (yy < 12) {
        int h0 = yy * 64;
        const float* Kb = g_K + tokbase;
        const float* Vb = g_V + tokbase;
#pragma unroll
        for (int rr = 0; rr < 4; rr++) {
            int idx = t + rr * 256;
            int c = idx >> 4, l = (idx & 15) * 4;
            *(float4*)&smA[c][l] = *(const float4*)(Kb + (size_t)c * HD + h0 + l);
            *(float4*)&smB[c][l] = *(const float4*)(Vb + (size_t)c * HD + d0 + l);
        }
        __syncthreads();
        float acc[4][4];
#pragma unroll
        for (int i = 0; i < 4; i++)
#pragma unroll
            for (int j = 0; j < 4; j++) acc[i][j] = 0.0f;
        for (int c = 0; c < 64; c++) {
            float a[4], bf[4];
            *(float4*)a  = *(const float4*)&smA[c][ty * 4];
            *(float4*)bf = *(const float4*)&smB[c][tx * 4];
#pragma unroll
            for (int i = 0; i < 4; i++)
#pragma unroll
                for (int j = 0; j < 4; j++)
                    acc[i][j] = fmaf(a[i], bf[j], acc[i][j]);
        }
        const float* ap = g_a + b * HD + d0;
        float aval[4];
#pragma unroll
        for (int j = 0; j < 4; j++) aval[j] = ap[tx * 4 + j];
        size_t sbase = (size_t)b * HD * HD + (size_t)h0 * HD + d0;
#pragma unroll
        for (int i = 0; i < 4; i++) {
            size_t rowo = sbase + (size_t)(ty * 4 + i) * HD + tx * 4;
            float4 sv = *(const float4*)(Sc + rowo);
            float4 nv;
            nv.x = sv.x * aval[0] + acc[i][0];
            nv.y = sv.y * aval[1] + acc[i][1];
            nv.z = sv.z * aval[2] + acc[i][2];
            nv.w = sv.w * aval[3] + acc[i][3];
            *(float4*)(Sn + rowo) = nv;
        }
    } else {
        if (nb == 0) return;
        int hc = yy - 12;
        const float* Qb = g_Q + tokbase;
        const float* Sb = Sc + (size_t)b * HD * HD;
        float acc[4][4];
#pragma unroll
        for (int i = 0; i < 4; i++)
#pragma unroll
            for (int j = 0; j < 4; j++) acc[i][j] = 0.0f;
        for (int hb = 0; hb < 3; hb++) {
            int h0 = hc * 192 + hb * 64;
#pragma unroll
            for (int rr = 0; rr < 4; rr++) {
                int idx = t + rr * 256;
                int rrow = idx >> 4, l = (idx & 15) * 4;
                float4 qv = *(const float4*)(Qb + (size_t)rrow * HD + h0 + l);
                smA[l + 0][rrow] = qv.x; smA[l + 1][rrow] = qv.y;
                smA[l + 2][rrow] = qv.z; smA[l + 3][rrow] = qv.w;
                *(float4*)&smB[rrow][l] =
                    *(const float4*)(Sb + (size_t)(h0 + rrow) * HD + d0 + l);
            }
            __syncthreads();
            for (int hh = 0; hh < 64; hh++) {
                float a[4], bf[4];
                *(float4*)a  = *(const float4*)&smA[hh][ty * 4];
                *(float4*)bf = *(const float4*)&smB[hh][tx * 4];
#pragma unroll
                for (int i = 0; i < 4; i++)
#pragma unroll
                    for (int j = 0; j < 4; j++)
                        acc[i][j] = fmaf(a[i], bf[j], acc[i][j]);
            }
            __syncthreads();
        }
        const float* ap = g_a + b * HD + d0;
        float aval[4];
#pragma unroll
        for (int j = 0; j < 4; j++) aval[j] = ap[tx * 4 + j];
        size_t obase = tokbase + d0;
#pragma unroll
        for (int i = 0; i < 4; i++)
#pragma unroll
            for (int j = 0; j < 4; j++)
                atomicAdd(&out[obase + (size_t)(ty * 4 + i) * HD + tx * 4 + j],
                          acc[i][j] * aval[j]);
    }
}

// ================= launch =================
extern "C" void kernel_launch(void* const* d_in, const int* in_sizes, int n_in,
                              void* d_out, int out_size)
{
    const float* x  = (const float*)d_in[0];
    const float* Wq = (const float*)d_in[1];
    const float* Wk = (const float*)d_in[2];
    const float* Wv = (const float*)d_in[3];
    const float* W1 = (const float*)d_in[4];
    const float* W2 = (const float*)d_in[5];
    const float* bv = (const float*)d_in[6];
    float* out = (float*)d_out;

    cudaFuncSetAttribute((const void*)qkv_mma_kernel,
                         cudaFuncAttributeMaxDynamicSharedMemorySize, 81920);
    cudaFuncSetAttribute((const void*)alpha_kernel,
                         cudaFuncAttributeMaxDynamicSharedMemorySize, 98304);

    zero_kernel<<<4608, 1024>>>();
    convert_x_kernel<<<6144, 256>>>(x);
    convert_w_kernel<<<dim3(64, 1, 3), 256>>>(Wq, Wk, Wv);

    // grid: n-tile fastest (6), then m-tile (256), then matrix (3)
    qkv_mma_kernel<<<dim3(6, 256, 3), 256, 81920>>>();

    alpha_kernel<<<BB * 64, 256, 98304>>>(x, W1, W2, bv);

    attn_kernel<<<dim3(NBLK, BB), 256>>>(out);

    for (int nb = 0; nb < NBLK; nb++)
        step_kernel<<<dim3(12, 16, BB), 256>>>(nb, out);
}

// round 4
// speedup vs baseline: 3.6402x; 1.7567x over previous
#include <cuda_runtime.h>
#include <cuda_bf16.h>
#include <math.h>
#include <stdint.h>

#define BB   8
#define SSEQ 4096
#define HD   768
#define CBLK 64
#define NBLK 64

// ---- device scratch ----
__device__ float g_Q[(size_t)BB*SSEQ*HD];
__device__ float g_K[(size_t)BB*SSEQ*HD];
__device__ float g_V[(size_t)BB*SSEQ*HD];
__device__ float g_a[BB*HD];
__device__ __nv_bfloat16 g_xh[(size_t)BB*SSEQ*HD];
__device__ __nv_bfloat16 g_xl[(size_t)BB*SSEQ*HD];
__device__ __nv_bfloat16 g_Wth[3*HD*HD];
__device__ __nv_bfloat16 g_Wtl[3*HD*HD];
// scan machinery
__device__ __nv_bfloat16 g_Qh[(size_t)BB*SSEQ*HD];
__device__ __nv_bfloat16 g_Ql[(size_t)BB*SSEQ*HD];
__device__ __nv_bfloat16 g_Kh[(size_t)BB*SSEQ*HD];
__device__ __nv_bfloat16 g_Kl[(size_t)BB*SSEQ*HD];
__device__ __nv_bfloat16 g_Vsh[(size_t)BB*SSEQ*HD];   // V * a^{-j_local}
__device__ __nv_bfloat16 g_Vsl[(size_t)BB*SSEQ*HD];
__device__ float g_T[(size_t)BB*7*HD*HD];             // chunk totals [b][g][d][h]
__device__ __nv_bfloat16 g_Sh[(size_t)BB*7*HD*HD];    // S_init slots [b][g-1][d][h]
__device__ __nv_bfloat16 g_Sl[(size_t)BB*7*HD*HD];
__device__ float g_apow[9*BB*HD];                     // a^p, p=0..8
__device__ float g_ainv[8*BB*HD];                     // a^{-j}, j=0..7

__device__ __forceinline__ uint32_t smem_u32(const void* p) {
    uint32_t a;
    asm("{ .reg .u64 t; cvta.to.shared.u64 t, %1; cvt.u32.u64 %0, t; }"
        : "=r"(a) : "l"(p));
    return a;
}
__device__ __forceinline__ void ldsm_x4(uint32_t (&r)[4], uint32_t addr) {
    asm volatile("ldmatrix.sync.aligned.m8n8.x4.shared.b16 {%0,%1,%2,%3}, [%4];"
                 : "=r"(r[0]), "=r"(r[1]), "=r"(r[2]), "=r"(r[3]) : "r"(addr));
}
__device__ __forceinline__ void ldsm_x4_t(uint32_t (&r)[4], uint32_t addr) {
    asm volatile("ldmatrix.sync.aligned.m8n8.x4.trans.shared.b16 {%0,%1,%2,%3}, [%4];"
                 : "=r"(r[0]), "=r"(r[1]), "=r"(r[2]), "=r"(r[3]) : "r"(addr));
}
__device__ __forceinline__ void mma_bf16(float (&c)[4], const uint32_t a[4],
                                         const uint32_t b0, const uint32_t b1) {
    asm volatile(
        "mma.sync.aligned.m16n8k16.row.col.f32.bf16.bf16.f32 "
        "{%0,%1,%2,%3}, {%4,%5,%6,%7}, {%8,%9}, {%0,%1,%2,%3};"
        : "+f"(c[0]), "+f"(c[1]), "+f"(c[2]), "+f"(c[3])
        : "r"(a[0]), "r"(a[1]), "r"(a[2]), "r"(a[3]), "r"(b0), "r"(b1));
}
__device__ __forceinline__ void cpasync16(uint32_t sa, const void* gp) {
    asm volatile("cp.async.cg.shared.global [%0], [%1], 16;" :: "r"(sa), "l"(gp));
}

// ================= conversion kernels =================
__global__ void convert_x_kernel(const float* __restrict__ x) {
    size_t n4 = (size_t)BB * SSEQ * HD / 4;
    for (size_t i = (size_t)blockIdx.x * blockDim.x + threadIdx.x; i < n4;
         i += (size_t)gridDim.x * blockDim.x) {
        float4 v = ((const float4*)x)[i];
        __nv_bfloat16 h0 = __float2bfloat16(v.x);
        __nv_bfloat16 h1 = __float2bfloat16(v.y);
        __nv_bfloat16 h2 = __float2bfloat16(v.z);
        __nv_bfloat16 h3 = __float2bfloat16(v.w);
        __nv_bfloat16 l0 = __float2bfloat16(v.x - __bfloat162float(h0));
        __nv_bfloat16 l1 = __float2bfloat16(v.y - __bfloat162float(h1));
        __nv_bfloat16 l2 = __float2bfloat16(v.z - __bfloat162float(h2));
        __nv_bfloat16 l3 = __float2bfloat16(v.w - __bfloat162float(h3));
        __nv_bfloat162 ph0; ph0.x = h0; ph0.y = h1;
        __nv_bfloat162 ph1; ph1.x = h2; ph1.y = h3;
        __nv_bfloat162 pl0; pl0.x = l0; pl0.y = l1;
        __nv_bfloat162 pl1; pl1.x = l2; pl1.y = l3;
        ((__nv_bfloat162*)g_xh)[2*i]   = ph0;
        ((__nv_bfloat162*)g_xh)[2*i+1] = ph1;
        ((__nv_bfloat162*)g_xl)[2*i]   = pl0;
        ((__nv_bfloat162*)g_xl)[2*i+1] = pl1;
    }
}

__global__ void convert_w_kernel(const float* __restrict__ Wq,
                                 const float* __restrict__ Wk,
                                 const float* __restrict__ Wv) {
    int w = blockIdx.z;
    const float* W = (w == 0) ? Wq : ((w == 1) ? Wk : Wv);
    __nv_bfloat16* th = g_Wth + (size_t)w * HD * HD;
    __nv_bfloat16* tl = g_Wtl + (size_t)w * HD * HD;
    for (int idx = blockIdx.x * 256 + threadIdx.x; idx < HD * HD; idx += gridDim.x * 256) {
        int k = idx / HD, n = idx % HD;
        float v = W[idx];
        __nv_bfloat16 hi = __float2bfloat16(v);
        __nv_bfloat16 lo = __float2bfloat16(v - __bfloat162float(hi));
        th[(size_t)n * HD + k] = hi;
        tl[(size_t)n * HD + k] = lo;
    }
}

// Q,K -> hi/lo bf16; V -> V*a^{-j_local} hi/lo
__global__ void convert_qkv_kernel() {
    size_t n4 = (size_t)BB * SSEQ * HD / 4;
    for (size_t i = (size_t)blockIdx.x * blockDim.x + threadIdx.x; i < n4;
         i += (size_t)gridDim.x * blockDim.x) {
        size_t elem = i * 4;
        int d = (int)(elem % HD);
        size_t row = elem / HD;
        int s = (int)(row % SSEQ);
        int b = (int)(row / SSEQ);
        int j = (s >> 6) & 7;
        const float* ai = g_ainv + ((size_t)j * BB + b) * HD + d;

        float4 q = ((const float4*)g_Q)[i];
        float4 k = ((const float4*)g_K)[i];
        float4 v = ((const float4*)g_V)[i];
        float4 av = *(const float4*)ai;
        v.x *= av.x; v.y *= av.y; v.z *= av.z; v.w *= av.w;

        float* qf = (float*)&q; float* kf = (float*)&k; float* vf = (float*)&v;
        __nv_bfloat16 qh[4], ql[4], kh[4], kl[4], vh[4], vl[4];
#pragma unroll
        for (int e = 0; e < 4; e++) {
            qh[e] = __float2bfloat16(qf[e]); ql[e] = __float2bfloat16(qf[e] - __bfloat162float(qh[e]));
            kh[e] = __float2bfloat16(kf[e]); kl[e] = __float2bfloat16(kf[e] - __bfloat162float(kh[e]));
            vh[e] = __float2bfloat16(vf[e]); vl[e] = __float2bfloat16(vf[e] - __bfloat162float(vh[e]));
        }
        *(uint2*)&g_Qh[elem] = *(uint2*)qh;  *(uint2*)&g_Ql[elem] = *(uint2*)ql;
        *(uint2*)&g_Kh[elem] = *(uint2*)kh;  *(uint2*)&g_Kl[elem] = *(uint2*)kl;
        *(uint2*)&g_Vsh[elem] = *(uint2*)vh; *(uint2*)&g_Vsl[elem] = *(uint2*)vl;
    }
}

// ================= zero + powers =================
__global__ void zero_a_kernel() {
    int idx = blockIdx.x * blockDim.x + threadIdx.x;
    if (idx < BB * HD) g_a[idx] = 0.0f;
}
__global__ void powers_kernel() {
    int idx = blockIdx.x * blockDim.x + threadIdx.x;
    if (idx >= BB * HD) return;
    int b = idx / HD, d = idx % HD;
    float a = g_a[idx];
    float p = 1.0f;
#pragma unroll
    for (int q = 0; q <= 8; q++) { g_apow[((size_t)q * BB + b) * HD + d] = p; p *= a; }
    float ia = 1.0f / a, pv = 1.0f;
#pragma unroll
    for (int q = 0; q < 8; q++) { g_ainv[((size_t)q * BB + b) * HD + d] = pv; pv *= ia; }
}

// ================= QKV via mma.sync bf16x3 (unchanged from R3) =================
#define QKV_STRIDE 40
#define QKV_ARR_BYTES 10240
#define QKV_STAGE_BYTES 40960

__global__ __launch_bounds__(256) void qkv_mma_kernel() {
    extern __shared__ char sm[];
    uint32_t smb = smem_u32(sm);
    int t = threadIdx.x, lane = t & 31, w = t >> 5;
    int wm = w & 1, wn = w >> 1;
    int nb = blockIdx.x * 128;
    int mb = blockIdx.y * 128;
    int mat = blockIdx.z;
    const __nv_bfloat16* Bh_g = g_Wth + (size_t)mat * HD * HD;
    const __nv_bfloat16* Bl_g = g_Wtl + (size_t)mat * HD * HD;
    float* outp = (mat == 0) ? g_Q : ((mat == 1) ? g_K : g_V);

    float acc[4][4][4];
#pragma unroll
    for (int i = 0; i < 4; i++)
#pragma unroll
        for (int j = 0; j < 4; j++)
#pragma unroll
            for (int q = 0; q < 4; q++) acc[i][j][q] = 0.0f;

    auto issue = [&](int s, int k0) {
#pragma unroll
        for (int q = 0; q < 8; q++) {
            int id = t + q * 256;
            int arr = id >> 9, rem = id & 511;
            int row = rem >> 2, c = (rem & 3) * 8;
            const __nv_bfloat16* gp;
            if (arr == 0)      gp = g_xh + (size_t)(mb + row) * HD + k0 + c;
            else if (arr == 1) gp = g_xl + (size_t)(mb + row) * HD + k0 + c;
            else if (arr == 2) gp = Bh_g + (size_t)(nb + row) * HD + k0 + c;
            else               gp = Bl_g + (size_t)(nb + row) * HD + k0 + c;
            uint32_t sa = smb + s * QKV_STAGE_BYTES + arr * QKV_ARR_BYTES
                        + (row * QKV_STRIDE + c) * 2;
            cpasync16(sa, gp);
        }
        asm volatile("cp.async.commit_group;");
    };

    issue(0, 0);

    int aRow = wm * 64 + (lane & 15);
    int aColSel = (lane >> 4) * 8;
    int bRow = wn * 32 + (lane & 7) + ((lane >> 4) << 3);
    int bColSel = ((lane >> 3) & 1) * 8;

    for (int it = 0; it < 24; it++) {
        int s = it & 1;
        if (it + 1 < 24) {
            issue(1 - s, (it + 1) * 32);
            asm volatile("cp.async.wait_group 1;");
        } else {
            asm volatile("cp.async.wait_group 0;");
        }
        __syncthreads();

        uint32_t stage = smb + s * QKV_STAGE_BYTES;
#pragma unroll
        for (int kk = 0; kk < 2; kk++) {
            int aCol = kk * 16 + aColSel;
            int bCol = kk * 16 + bColSel;
            uint32_t ah[4][4], al[4][4];
#pragma unroll
            for (int mf = 0; mf < 4; mf++) {
                uint32_t addr = stage + ((aRow + mf * 16) * QKV_STRIDE + aCol) * 2;
                ldsm_x4(ah[mf], addr);
                ldsm_x4(al[mf], addr + QKV_ARR_BYTES);
            }
            uint32_t bh[4][2], bl[4][2];
#pragma unroll
            for (int ng = 0; ng < 2; ng++) {
                uint32_t addr = stage + 2 * QKV_ARR_BYTES
                              + ((bRow + ng * 16) * QKV_STRIDE + bCol) * 2;
                uint32_t r[4];
                ldsm_x4(r, addr);
                bh[2*ng][0] = r[0]; bh[2*ng][1] = r[1];
                bh[2*ng+1][0] = r[2]; bh[2*ng+1][1] = r[3];
                ldsm_x4(r, addr + QKV_ARR_BYTES);
                bl[2*ng][0] = r[0]; bl[2*ng][1] = r[1];
                bl[2*ng+1][0] = r[2]; bl[2*ng+1][1] = r[3];
            }
#pragma unroll
            for (int mf = 0; mf < 4; mf++)
#pragma unroll
                for (int nf = 0; nf < 4; nf++) {
                    mma_bf16(acc[mf][nf], ah[mf], bh[nf][0], bh[nf][1]);
                    mma_bf16(acc[mf][nf], ah[mf], bl[nf][0], bl[nf][1]);
                    mma_bf16(acc[mf][nf], al[mf], bh[nf][0], bh[nf][1]);
                }
        }
        __syncthreads();
    }

    int g = lane >> 2, tig = lane & 3;
#pragma unroll
    for (int mf = 0; mf < 4; mf++) {
#pragma unroll
        for (int nf = 0; nf < 4; nf++) {
            int row = mb + wm * 64 + mf * 16 + g;
            int col = nb + wn * 32 + nf * 8 + tig * 2;
            float* p0 = outp + (size_t)row * HD + col;
            float* p1 = outp + (size_t)(row + 8) * HD + col;
            *(float2*)p0 = make_float2(acc[mf][nf][0], acc[mf][nf][1]);
            *(float2*)p1 = make_float2(acc[mf][nf][2], acc[mf][nf][3]);
        }
    }
}

// ================= gate alpha =================
__global__ __launch_bounds__(256) void alpha_kernel(
    const float* __restrict__ x,
    const float* __restrict__ W1,
    const float* __restrict__ W2,
    const float* __restrict__ bvec)
{
    extern __shared__ float smf[];
    float* W1s = smf;
    float* W2s = smf + HD * 16;
    int t = threadIdx.x;
    for (int i = t; i < HD * 16; i += 256) { W1s[i] = W1[i]; W2s[i] = W2[i]; }
    __syncthreads();

    int b = blockIdx.x >> 6;
    int rowblk = blockIdx.x & 63;
    int w = t >> 5, lane = t & 31;

    float acc[24];
#pragma unroll
    for (int q = 0; q < 24; q++) acc[q] = 0.0f;

    for (int r = 0; r < 8; r++) {
        int row = rowblk * 64 + w * 8 + r;
        const float* xr = x + ((size_t)b * SSEQ + row) * HD;
        float tp[16];
#pragma unroll
        for (int j = 0; j < 16; j++) tp[j] = 0.0f;
        for (int i = lane; i < HD; i += 32) {
            float xv = xr[i];
            const float* w1r = &W1s[i * 16];
#pragma unroll
            for (int j = 0; j < 16; j++) tp[j] = fmaf(xv, w1r[j], tp[j]);
        }
#pragma unroll
        for (int off = 16; off > 0; off >>= 1)
#pragma unroll
            for (int j = 0; j < 16; j++)
                tp[j] += __shfl_xor_sync(0xffffffffu, tp[j], off);
#pragma unroll
        for (int q = 0; q < 24; q++) {
            int d = lane + q * 32;
            float h = bvec[d];
#pragma unroll
            for (int j = 0; j < 16; j++) h = fmaf(tp[j], W2s[j * HD + d], h);
            float sig = 1.0f / (1.0f + expf(-h));
            float v = sqrtf(sqrtf(sqrtf(sqrtf(sig))));
            acc[q] += v;
        }
    }
    const float inv = 1.0f / (float)SSEQ;
#pragma unroll
    for (int q = 0; q < 24; q++) {
        int d = lane + q * 32;
        atomicAdd(&g_a[b * HD + d], acc[q] * inv);
    }
}

// ================= intra-block attention (diag blocks) =================
__global__ __launch_bounds__(256) void attn_kernel(float* __restrict__ out) {
    __shared__ float Ps[64][65];
    __shared__ float buf[64][68];
    int nb = blockIdx.x, b = blockIdx.y;
    int t = threadIdx.x, tx = t & 15, ty = t >> 4;
    size_t base = ((size_t)b * SSEQ + (size_t)nb * CBLK) * HD;
    const float* Qb = g_Q + base;
    const float* Kb = g_K + base;
    const float* Vb = g_V + base;

    float acc[4][4];
#pragma unroll
    for (int i = 0; i < 4; i++)
#pragma unroll
        for (int j = 0; j < 4; j++) acc[i][j] = 0.0f;

    for (int h0 = 0; h0 < HD; h0 += 32) {
#pragma unroll
        for (int rr = 0; rr < 2; rr++) {
            int idx = t + rr * 256;
            int c = idx >> 3, hl = (idx & 7) * 4;
            float4 qv = *(const float4*)(Qb + (size_t)c * HD + h0 + hl);
            float4 kv = *(const float4*)(Kb + (size_t)c * HD + h0 + hl);
            buf[hl + 0][c] = qv.x; buf[hl + 1][c] = qv.y;
            buf[hl + 2][c] = qv.z; buf[hl + 3][c] = qv.w;
            buf[32 + hl + 0][c] = kv.x; buf[32 + hl + 1][c] = kv.y;
            buf[32 + hl + 2][c] = kv.z; buf[32 + hl + 3][c] = kv.w;
        }
        __syncthreads();
#pragma unroll
        for (int hh = 0; hh < 32; hh++) {
            float a[4], bf[4];
            *(float4*)a  = *(const float4*)&buf[hh][ty * 4];
            *(float4*)bf = *(const float4*)&buf[32 + hh][tx * 4];
#pragma unroll
            for (int i = 0; i < 4; i++)
#pragma unroll
                for (int j = 0; j < 4; j++)
                    acc[i][j] = fmaf(a[i], bf[j], acc[i][j]);
        }
        __syncthreads();
    }
#pragma unroll
    for (int i = 0; i < 4; i++)
#pragma unroll
        for (int j = 0; j < 4; j++)
            Ps[ty * 4 + i][tx * 4 + j] = acc[i][j];
    __syncthreads();

    {
        int w = t >> 5, lane = t & 31;
        const float scale = 1.0f / 27.712813f;
#pragma unroll
        for (int r8 = 0; r8 < 8; r8++) {
            int r = w * 8 + r8;
            float p0 = Ps[r][lane], p1 = Ps[r][lane + 32];
            float s0 = (lane <= r)        ? p0 * scale : 0.0f;
            float s1 = ((lane + 32) <= r) ? p1 * scale : 0.0f;
            float m = fmaxf(s0, s1);
#pragma unroll
            for (int off = 16; off; off >>= 1)
                m = fmaxf(m, __shfl_xor_sync(0xffffffffu, m, off));
            float e0 = expf(s0 - m), e1 = expf(s1 - m);
            float ssum = e0 + e1;
#pragma unroll
            for (int off = 16; off; off >>= 1)
                ssum += __shfl_xor_sync(0xffffffffu, ssum, off);
            float invz = 1.0f / ssum;
            Ps[r][lane]      = p0 + e0 * invz;
            Ps[r][lane + 32] = p1 + e1 * invz;
        }
    }
    __syncthreads();

    for (int d0 = 0; d0 < HD; d0 += 64) {
#pragma unroll
        for (int rr = 0; rr < 4; rr++) {
            int idx = t + rr * 256;
            int c = idx >> 4, dl = (idx & 15) * 4;
            *(float4*)&buf[c][dl] = *(const float4*)(Vb + (size_t)c * HD + d0 + dl);
        }
        __syncthreads();
        float o[4][4];
#pragma unroll
        for (int i = 0; i < 4; i++)
#pragma unroll
            for (int j = 0; j < 4; j++) o[i][j] = 0.0f;
        for (int cp = 0; cp < 64; cp++) {
            float a[4], bf[4];
            a[0] = Ps[ty * 4 + 0][cp]; a[1] = Ps[ty * 4 + 1][cp];
            a[2] = Ps[ty * 4 + 2][cp]; a[3] = Ps[ty * 4 + 3][cp];
            *(float4*)bf = *(const float4*)&buf[cp][tx * 4];
#pragma unroll
            for (int i = 0; i < 4; i++)
#pragma unroll
                for (int j = 0; j < 4; j++)
                    o[i][j] = fmaf(a[i], bf[j], o[i][j]);
        }
#pragma unroll
        for (int i = 0; i < 4; i++) {
            float* op = out + base + (size_t)(ty * 4 + i) * HD + d0 + tx * 4;
            *(float4*)op = make_float4(o[i][0], o[i][1], o[i][2], o[i][3]);
        }
        __syncthreads();
    }
}

// ================= chunk totals: T[b][g][d][h] = a^7[d] * sum_c Vs[c,d]*K[c,h] ====
// Both operands k-major (c rows) -> trans ldmatrix. CTA 128x128, K=512 in 16 chunks.
#define CT_STRIDE 136
#define CT_ARR_BYTES 8704       // 32*136*2
#define CT_STAGE_BYTES 34816    // 4 arrays

__global__ __launch_bounds__(256) void chunk_total_kernel() {
    extern __shared__ char sm[];
    uint32_t smb = smem_u32(sm);
    int t = threadIdx.x, lane = t & 31, w = t >> 5;
    int wm = w & 1, wn = w >> 1;
    int tile = blockIdx.x;
    int m0 = (tile % 6) * 128;   // d
    int n0 = (tile / 6) * 128;   // h
    int bg = blockIdx.y;
    int b = bg / 7, g = bg % 7;
    size_t crow0 = (size_t)b * SSEQ + (size_t)g * 512;

    float acc[4][4][4];
#pragma unroll
    for (int i = 0; i < 4; i++)
#pragma unroll
        for (int j = 0; j < 4; j++)
#pragma unroll
            for (int q = 0; q < 4; q++) acc[i][j][q] = 0.0f;

    auto issue = [&](int s, int k0) {
#pragma unroll
        for (int q = 0; q < 8; q++) {
            int id = t + q * 256;
            int arr = id >> 9, rem = id & 511;
            int row = rem >> 4, c = (rem & 15) * 8;
            const __nv_bfloat16* gp;
            size_t go = (crow0 + k0 + row) * HD;
            if (arr == 0)      gp = g_Vsh + go + m0 + c;
            else if (arr == 1) gp = g_Vsl + go + m0 + c;
            else if (arr == 2) gp = g_Kh  + go + n0 + c;
            else               gp = g_Kl  + go + n0 + c;
            uint32_t sa = smb + s * CT_STAGE_BYTES + arr * CT_ARR_BYTES
                        + (row * CT_STRIDE + c) * 2;
            cpasync16(sa, gp);
        }
        asm volatile("cp.async.commit_group;");
    };

    issue(0, 0);

    // trans-load lane addressing
    int aMem_r = ((lane >> 4) << 3) + (lane & 7);      // + kk*16
    int aMem_c = wm * 64 + ((lane >> 3) & 1) * 8;      // + mf*16
    int bMem_r = ((lane >> 3) & 1) * 8 + (lane & 7);   // + kk*16
    int bMem_c = wn * 32 + (lane >> 4) * 8;            // + ng*16

    for (int it = 0; it < 16; it++) {
        int s = it & 1;
        if (it + 1 < 16) {
            issue(1 - s, (it + 1) * 32);
            asm volatile("cp.async.wait_group 1;");
        } else {
            asm volatile("cp.async.wait_group 0;");
        }
        __syncthreads();

        uint32_t stage = smb + s * CT_STAGE_BYTES;
#pragma unroll
        for (int kk = 0; kk < 2; kk++) {
            uint32_t ah[4][4], al[4][4];
#pragma unroll
            for (int mf = 0; mf < 4; mf++) {
                uint32_t addr = stage + ((kk * 16 + aMem_r) * CT_STRIDE
                              + aMem_c + mf * 16) * 2;
                ldsm_x4_t(ah[mf], addr);
                ldsm_x4_t(al[mf], addr + CT_ARR_BYTES);
            }
            uint32_t bh[4][2], bl[4][2];
#pragma unroll
            for (int ng = 0; ng < 2; ng++) {
                uint32_t addr = stage + 2 * CT_ARR_BYTES
                              + ((kk * 16 + bMem_r) * CT_STRIDE + bMem_c + ng * 16) * 2;
                uint32_t r[4];
                ldsm_x4_t(r, addr);
                bh[2*ng][0] = r[0]; bh[2*ng][1] = r[1];
                bh[2*ng+1][0] = r[2]; bh[2*ng+1][1] = r[3];
                ldsm_x4_t(r, addr + CT_ARR_BYTES);
                bl[2*ng][0] = r[0]; bl[2*ng][1] = r[1];
                bl[2*ng+1][0] = r[2]; bl[2*ng+1][1] = r[3];
            }
#pragma unroll
            for (int mf = 0; mf < 4; mf++)
#pragma unroll
                for (int nf = 0; nf < 4; nf++) {
                    mma_bf16(acc[mf][nf], ah[mf], bh[nf][0], bh[nf][1]);
                    mma_bf16(acc[mf][nf], ah[mf], bl[nf][0], bl[nf][1]);
                    mma_bf16(acc[mf][nf], al[mf], bh[nf][0], bh[nf][1]);
                }
        }
        __syncthreads();
    }

    // epilogue: scale by a^7[d] (d = m row)
    int gr = lane >> 2, tig = lane & 3;
    float* Tp = g_T + (size_t)bg * HD * HD;
    const float* a7 = g_apow + ((size_t)7 * BB + b) * HD;
#pragma unroll
    for (int mf = 0; mf < 4; mf++) {
        int d0r = m0 + wm * 64 + mf * 16 + gr;
        float s0 = a7[d0r], s1 = a7[d0r + 8];
#pragma unroll
        for (int nf = 0; nf < 4; nf++) {
            int col = n0 + wn * 32 + nf * 8 + tig * 2;
            float* p0 = Tp + (size_t)d0r * HD + col;
            float* p1 = Tp + (size_t)(d0r + 8) * HD + col;
            *(float2*)p0 = make_float2(acc[mf][nf][0] * s0, acc[mf][nf][1] * s0);
            *(float2*)p1 = make_float2(acc[mf][nf][2] * s1, acc[mf][nf][3] * s1);
        }
    }
}

// ================= sequential scan (one launch) =================
__global__ __launch_bounds__(256) void scan_kernel() {
    int b = blockIdx.y;
    int idx = blockIdx.x * 256 + threadIdx.x;  // over 768*768
    int d = idx / HD, h = idx % HD;
    float a8 = g_apow[((size_t)8 * BB + b) * HD + d];
    float carry = 0.0f;
    size_t base = ((size_t)b * 7) * HD * HD + (size_t)d * HD + h;
#pragma unroll
    for (int g = 0; g < 7; g++) {
        carry = fmaf(a8, carry, g_T[base + (size_t)g * HD * HD]);
        __nv_bfloat16 hi = __float2bfloat16(carry);
        __nv_bfloat16 lo = __float2bfloat16(carry - __bfloat162float(hi));
        g_Sh[base + (size_t)g * HD * HD] = hi;
        g_Sl[base + (size_t)g * HD * HD] = lo;
    }
}

// ================= inter-chunk: out += a^{delta+1} * (Q_chunk @ S_init) ========
__global__ __launch_bounds__(256) void inter_kernel(float* __restrict__ out) {
    extern __shared__ char sm[];
    uint32_t smb = smem_u32(sm);
    int t = threadIdx.x, lane = t & 31, w = t >> 5;
    int wm = w & 1, wn = w >> 1;
    int nb = blockIdx.x * 128;
    int mb = blockIdx.y * 128;
    int combo = blockIdx.z;
    int b = combo / 7, gm1 = combo % 7, g = gm1 + 1;
    size_t arow0 = (size_t)b * SSEQ + (size_t)g * 512 + mb;
    size_t srow0 = ((size_t)b * 7 + gm1) * HD * HD;

    float acc[4][4][4];
#pragma unroll
    for (int i = 0; i < 4; i++)
#pragma unroll
        for (int j = 0; j < 4; j++)
#pragma unroll
            for (int q = 0; q < 4; q++) acc[i][j][q] = 0.0f;

    auto issue = [&](int s, int k0) {
#pragma unroll
        for (int q = 0; q < 8; q++) {
            int id = t + q * 256;
            int arr = id >> 9, rem = id & 511;
            int row = rem >> 2, c = (rem & 3) * 8;
            const __nv_bfloat16* gp;
            if (arr == 0)      gp = g_Qh + (arow0 + row) * HD + k0 + c;
            else if (arr == 1) gp = g_Ql + (arow0 + row) * HD + k0 + c;
            else if (arr == 2) gp = g_Sh + srow0 + (size_t)(nb + row) * HD + k0 + c;
            else               gp = g_Sl + srow0 + (size_t)(nb + row) * HD + k0 + c;
            uint32_t sa = smb + s * QKV_STAGE_BYTES + arr * QKV_ARR_BYTES
                        + (row * QKV_STRIDE + c) * 2;
            cpasync16(sa, gp);
        }
        asm volatile("cp.async.commit_group;");
    };

    issue(0, 0);

    int aRow = wm * 64 + (lane & 15);
    int aColSel = (lane >> 4) * 8;
    int bRow = wn * 32 + (lane & 7) + ((lane >> 4) << 3);
    int bColSel = ((lane >> 3) & 1) * 8;

    for (int it = 0; it < 24; it++) {
        int s = it & 1;
        if (it + 1 < 24) {
            issue(1 - s, (it + 1) * 32);
            asm volatile("cp.async.wait_group 1;");
        } else {
            asm volatile("cp.async.wait_group 0;");
        }
        __syncthreads();

        uint32_t stage = smb + s * QKV_STAGE_BYTES;
#pragma unroll
        for (int kk = 0; kk < 2; kk++) {
            int aCol = kk * 16 + aColSel;
            int bCol = kk * 16 + bColSel;
            uint32_t ah[4][4], al[4][4];
#pragma unroll
            for (int mf = 0; mf < 4; mf++) {
                uint32_t addr = stage + ((aRow + mf * 16) * QKV_STRIDE + aCol) * 2;
                ldsm_x4(ah[mf], addr);
                ldsm_x4(al[mf], addr + QKV_ARR_BYTES);
            }
            uint32_t bh[4][2], bl[4][2];
#pragma unroll
            for (int ng = 0; ng < 2; ng++) {
                uint32_t addr = stage + 2 * QKV_ARR_BYTES
                              + ((bRow + ng * 16) * QKV_STRIDE + bCol) * 2;
                uint32_t r[4];
                ldsm_x4(r, addr);
                bh[2*ng][0] = r[0]; bh[2*ng][1] = r[1];
                bh[2*ng+1][0] = r[2]; bh[2*ng+1][1] = r[3];
                ldsm_x4(r, addr + QKV_ARR_BYTES);
                bl[2*ng][0] = r[0]; bl[2*ng][1] = r[1];
                bl[2*ng+1][0] = r[2]; bl[2*ng+1][1] = r[3];
            }
#pragma unroll
            for (int mf = 0; mf < 4; mf++)
#pragma unroll
                for (int nf = 0; nf < 4; nf++) {
                    mma_bf16(acc[mf][nf], ah[mf], bh[nf][0], bh[nf][1]);
                    mma_bf16(acc[mf][nf], ah[mf], bl[nf][0], bl[nf][1]);
                    mma_bf16(acc[mf][nf], al[mf], bh[nf][0], bh[nf][1]);
                }
        }
        __syncthreads();
    }

    // epilogue: out += a^{delta+1}[d] * Y   (delta constant per warp m-half)
    int gr = lane >> 2, tig = lane & 3;
    int p = blockIdx.y * 2 + wm + 1;     // delta+1
    const float* sc = g_apow + ((size_t)p * BB + b) * HD;
#pragma unroll
    for (int mf = 0; mf < 4; mf++) {
        size_t row = arow0 + wm * 64 + mf * 16 + gr;
#pragma unroll
        for (int nf = 0; nf < 4; nf++) {
            int col = nb + wn * 32 + nf * 8 + tig * 2;
            float s0 = sc[col], s1 = sc[col + 1];
            float* p0 = out + row * HD + col;
            float* p1 = out + (row + 8) * HD + col;
            float2 v0 = *(float2*)p0, v1 = *(float2*)p1;
            v0.x += acc[mf][nf][0] * s0; v0.y += acc[mf][nf][1] * s1;
            v1.x += acc[mf][nf][2] * s0; v1.y += acc[mf][nf][3] * s1;
            *(float2*)p0 = v0; *(float2*)p1 = v1;
        }
    }
}

// ================= intra-chunk cross-block: out += a^t * sum_{j<t} P_tj @ Vs_j ===
#define IN_PSTRIDE 456
#define IN_PBYTES  58368       // 64*456*2
#define IN_STG     116736
#define IN_S1ARR   9216        // [64][72] bf16
#define IN_S2ARR   17408       // [64][136] bf16

__global__ __launch_bounds__(256) void intra_kernel(float* __restrict__ out) {
    extern __shared__ char sm[];
    uint32_t smb = smem_u32(sm);
    uint32_t Ph = smb, Pl = smb + IN_PBYTES, STG = smb + IN_STG;
    int t = threadIdx.x, lane = t & 31, w = t >> 5;
    int wm = w & 1, wn = w >> 1;
    int tt = blockIdx.x + 1;            // delta: 1..7
    int g = blockIdx.y, b = blockIdx.z;
    size_t qrow0 = (size_t)b * SSEQ + (size_t)(g * 8 + tt) * 64;
    size_t krow0 = (size_t)b * SSEQ + (size_t)g * 512;
    int gr = lane >> 2, tig = lane & 3;

    // ---------- stage 1: P_j = Q_t @ K_j^T, j = 0..tt-1 ----------
    for (int j = 0; j < tt; j++) {
        float pacc[2][2][4];
#pragma unroll
        for (int i = 0; i < 2; i++)
#pragma unroll
            for (int q = 0; q < 2; q++)
#pragma unroll
                for (int e = 0; e < 4; e++) pacc[i][q][e] = 0.0f;

        for (int kc = 0; kc < 12; kc++) {
            __syncthreads();
#pragma unroll
            for (int q = 0; q < 8; q++) {
                int id = t + q * 256;
                int arr = id >> 9, rem = id & 511;
                int row = rem >> 3, cc = (rem & 7) * 8;
                const __nv_bfloat16* gp;
                if (arr == 0)      gp = g_Qh + (qrow0 + row) * HD + kc * 64 + cc;
                else if (arr == 1) gp = g_Ql + (qrow0 + row) * HD + kc * 64 + cc;
                else if (arr == 2) gp = g_Kh + (krow0 + j * 64 + row) * HD + kc * 64 + cc;
                else               gp = g_Kl + (krow0 + j * 64 + row) * HD + kc * 64 + cc;
                cpasync16(STG + arr * IN_S1ARR + (row * 72 + cc) * 2, gp);
            }
            asm volatile("cp.async.commit_group;");
            asm volatile("cp.async.wait_group 0;");
            __syncthreads();

#pragma unroll
            for (int kk = 0; kk < 4; kk++) {
                uint32_t ah[2][4], al[2][4];
#pragma unroll
                for (int mf = 0; mf < 2; mf++) {
                    uint32_t addr = STG + ((wm * 32 + mf * 16 + (lane & 15)) * 72
                                  + kk * 16 + (lane >> 4) * 8) * 2;
                    ldsm_x4(ah[mf], addr);
                    ldsm_x4(al[mf], addr + IN_S1ARR);
                }
                uint32_t bh[2][2], bl[2][2];
                {
                    uint32_t addr = STG + 2 * IN_S1ARR
                                  + ((wn * 16 + (lane & 7) + ((lane >> 4) << 3)) * 72
                                  + kk * 16 + ((lane >> 3) & 1) * 8) * 2;
                    uint32_t r[4];
                    ldsm_x4(r, addr);
                    bh[0][0] = r[0]; bh[0][1] = r[1]; bh[1][0] = r[2]; bh[1][1] = r[3];
                    ldsm_x4(r, addr + IN_S1ARR);
                    bl[0][0] = r[0]; bl[0][1] = r[1]; bl[1][0] = r[2]; bl[1][1] = r[3];
                }
#pragma unroll
                for (int mf = 0; mf < 2; mf++)
#pragma unroll
                    for (int nf = 0; nf < 2; nf++) {
                        mma_bf16(pacc[mf][nf], ah[mf], bh[nf][0], bh[nf][1]);
                        mma_bf16(pacc[mf][nf], ah[mf], bl[nf][0], bl[nf][1]);
                        mma_bf16(pacc[mf][nf], al[mf], bh[nf][0], bh[nf][1]);
                    }
            }
        }
        // write P_j hi/lo to strip
#pragma unroll
        for (int mf = 0; mf < 2; mf++)
#pragma unroll
            for (int nf = 0; nf < 2; nf++) {
                int row = wm * 32 + mf * 16 + gr;
                int col = j * 64 + wn * 16 + nf * 8 + tig * 2;
#pragma unroll
                for (int half = 0; half < 2; half++) {
                    float v0 = pacc[mf][nf][half * 2], v1 = pacc[mf][nf][half * 2 + 1];
                    __nv_bfloat16 h0 = __float2bfloat16(v0);
                    __nv_bfloat16 h1 = __float2bfloat16(v1);
                    __nv_bfloat16 l0 = __float2bfloat16(v0 - __bfloat162float(h0));
                    __nv_bfloat16 l1 = __float2bfloat16(v1 - __bfloat162float(h1));
                    __nv_bfloat162 hp; hp.x = h0; hp.y = h1;
                    __nv_bfloat162 lp; lp.x = l0; lp.y = l1;
                    uint32_t off = ((row + half * 8) * IN_PSTRIDE + col) * 2;
                    *(__nv_bfloat162*)((char*)sm + (Ph - smb) + off) = hp;
                    *(__nv_bfloat162*)((char*)sm + (Pl - smb) + off) = lp;
                }
            }
    }
    __syncthreads();

    // ---------- stage 2: out_tile += a^tt[d] * P @ Vs ----------
    const float* sc = g_apow + ((size_t)tt * BB + b) * HD;
    for (int dt = 0; dt < 6; dt++) {
        float oacc[2][4][4];
#pragma unroll
        for (int i = 0; i < 2; i++)
#pragma unroll
            for (int q = 0; q < 4; q++)
#pragma unroll
                for (int e = 0; e < 4; e++) oacc[i][q][e] = 0.0f;

        for (int ec = 0; ec < tt; ec++) {
            __syncthreads();
#pragma unroll
            for (int q = 0; q < 8; q++) {
                int id = t + q * 256;
                int arr = id >> 10, rem = id & 1023;
                int row = rem >> 4, cc = (rem & 15) * 8;
                const __nv_bfloat16* gp = (arr == 0)
                    ? g_Vsh + (krow0 + ec * 64 + row) * HD + dt * 128 + cc
                    : g_Vsl + (krow0 + ec * 64 + row) * HD + dt * 128 + cc;
                cpasync16(STG + arr * IN_S2ARR + (row * 136 + cc) * 2, gp);
            }
            asm volatile("cp.async.commit_group;");
            asm volatile("cp.async.wait_group 0;");
            __syncthreads();

#pragma unroll
            for (int kk = 0; kk < 4; kk++) {
                uint32_t ah[2][4], al[2][4];
#pragma unroll
                for (int mf = 0; mf < 2; mf++) {
                    uint32_t addr = Ph + ((wm * 32 + mf * 16 + (lane & 15)) * IN_PSTRIDE
                                  + ec * 64 + kk * 16 + (lane >> 4) * 8) * 2;
                    ldsm_x4(ah[mf], addr);
                    ldsm_x4(al[mf], addr + IN_PBYTES);
                }
                uint32_t bh[4][2], bl[4][2];
#pragma unroll
                for (int ng = 0; ng < 2; ng++) {
                    uint32_t addr = STG + ((kk * 16 + ((lane >> 3) & 1) * 8 + (lane & 7)) * 136
                                  + wn * 32 + ng * 16 + (lane >> 4) * 8) * 2;
                    uint32_t r[4];
                    ldsm_x4_t(r, addr);
                    bh[2*ng][0] = r[0]; bh[2*ng][1] = r[1];
                    bh[2*ng+1][0] = r[2]; bh[2*ng+1][1] = r[3];
                    ldsm_x4_t(r, addr + IN_S2ARR);
                    bl[2*ng][0] = r[0]; bl[2*ng][1] = r[1];
                    bl[2*ng+1][0] = r[2]; bl[2*ng+1][1] = r[3];
                }
#pragma unroll
                for (int mf = 0; mf < 2; mf++)
#pragma unroll
                    for (int nf = 0; nf < 4; nf++) {
                        mma_bf16(oacc[mf][nf], ah[mf], bh[nf][0], bh[nf][1]);
                        mma_bf16(oacc[mf][nf], al[mf], bh[nf][0], bh[nf][1]);
                        mma_bf16(oacc[mf][nf], ah[mf], bl[nf][0], bl[nf][1]);
                    }
            }
        }
        // epilogue RMW
#pragma unroll
        for (int mf = 0; mf < 2; mf++) {
            size_t row = qrow0 + wm * 32 + mf * 16 + gr;
#pragma unroll
            for (int nf = 0; nf < 4; nf++) {
                int col = dt * 128 + wn * 32 + nf * 8 + tig * 2;
                float s0 = sc[col], s1 = sc[col + 1];
                float* p0 = out + row * HD + col;
                float* p1 = out + (row + 8) * HD + col;
                float2 v0 = *(float2*)p0, v1 = *(float2*)p1;
                v0.x += oacc[mf][nf][0] * s0; v0.y += oacc[mf][nf][1] * s1;
                v1.x += oacc[mf][nf][2] * s0; v1.y += oacc[mf][nf][3] * s1;
                *(float2*)p0 = v0; *(float2*)p1 = v1;
            }
        }
    }
}

// ================= launch =================
extern "C" void kernel_launch(void* const* d_in, const int* in_sizes, int n_in,
                              void* d_out, int out_size)
{
    const float* x  = (const float*)d_in[0];
    const float* Wq = (const float*)d_in[1];
    const float* Wk = (const float*)d_in[2];
    const float* Wv = (const float*)d_in[3];
    const float* W1 = (const float*)d_in[4];
    const float* W2 = (const float*)d_in[5];
    const float* bv = (const float*)d_in[6];
    float* out = (float*)d_out;

    cudaFuncSetAttribute((const void*)qkv_mma_kernel,
                         cudaFuncAttributeMaxDynamicSharedMemorySize, 81920);
    cudaFuncSetAttribute((const void*)inter_kernel,
                         cudaFuncAttributeMaxDynamicSharedMemorySize, 81920);
    cudaFuncSetAttribute((const void*)chunk_total_kernel,
                         cudaFuncAttributeMaxDynamicSharedMemorySize, 69632);
    cudaFuncSetAttribute((const void*)intra_kernel,
                         cudaFuncAttributeMaxDynamicSharedMemorySize, 153600);
    cudaFuncSetAttribute((const void*)alpha_kernel,
                         cudaFuncAttributeMaxDynamicSharedMemorySize, 98304);

    zero_a_kernel<<<24, 256>>>();
    convert_x_kernel<<<6144, 256>>>(x);
    convert_w_kernel<<<dim3(64, 1, 3), 256>>>(Wq, Wk, Wv);
    alpha_kernel<<<BB * 64, 256, 98304>>>(x, W1, W2, bv);
    powers_kernel<<<24, 256>>>();

    qkv_mma_kernel<<<dim3(6, 256, 3), 256, 81920>>>();
    convert_qkv_kernel<<<6144, 256>>>();

    attn_kernel<<<dim3(NBLK, BB), 256>>>(out);

    chunk_total_kernel<<<dim3(36, 56), 256, 69632>>>();
    scan_kernel<<<dim3(2304, BB), 256>>>();
    inter_kernel<<<dim3(6, 4, 56), 256, 81920>>>(out);
    intra_kernel<<<dim3(7, 8, 8), 256, 153600>>>(out);
}